// round 4
// baseline (speedup 1.0000x reference)
#include <cuda_runtime.h>
#include <math.h>

#define NNODES 100000
#define NEDGES 1600000
#define FIN    128
#define F1     64
#define H1N    8
#define F2     64
#define NEG_SLOPE 0.2f
#define DEGCAP 64
#define CO     80     // extended GEMM output columns: 64 h + 8 as + 8 ad (L2: 64+1+1+pad)

// ---------------- scratch (device globals; no allocation allowed) ----------------
__device__ float g_h1 [NNODES * F1];
__device__ float g_as1[NNODES * H1N];
__device__ float g_ad1[NNODES * H1N];
__device__ float g_f2 [NNODES * F1];
__device__ float g_h2 [NNODES * F2];
__device__ float g_as2[NNODES];
__device__ float g_ad2[NNODES];
__device__ int   g_cnt[NNODES];
__device__ int   g_adj[NNODES * DEGCAP];
__device__ float g_W1e[FIN * CO];
__device__ float g_W2e[F1 * CO];

// exp(leaky_relu(e)); lrelu(e) == max(e, 0.2*e)
__device__ __forceinline__ float pe(float e) {
    return __expf(fmaxf(e, NEG_SLOPE * e));
}

// ---------------- weight-extension prep (tiny) ----------------
__global__ void prep1_kernel(const float* __restrict__ W1,
                             const float* __restrict__ a_src1,
                             const float* __restrict__ a_dst1) {
    int idx = blockIdx.x * blockDim.x + threadIdx.x;
    if (idx >= FIN * CO) return;
    int k = idx / CO, c = idx % CO;
    float v;
    if (c < 64) {
        v = W1[k * 64 + c];
    } else if (c < 72) {
        int h = c - 64; v = 0.f;
        #pragma unroll
        for (int j = 0; j < 8; j++) v = fmaf(W1[k * 64 + h * 8 + j], a_src1[h * 8 + j], v);
    } else {
        int h = c - 72; v = 0.f;
        #pragma unroll
        for (int j = 0; j < 8; j++) v = fmaf(W1[k * 64 + h * 8 + j], a_dst1[h * 8 + j], v);
    }
    g_W1e[idx] = v;
}

__global__ void prep2_kernel(const float* __restrict__ W2,
                             const float* __restrict__ a_src2,
                             const float* __restrict__ a_dst2) {
    int idx = blockIdx.x * blockDim.x + threadIdx.x;
    if (idx >= F1 * CO) return;
    int k = idx / CO, c = idx % CO;
    float v = 0.f;
    if (c < 64) {
        v = W2[k * 64 + c];
    } else if (c == 64) {
        #pragma unroll
        for (int j = 0; j < 64; j++) v = fmaf(W2[k * 64 + j], a_src2[j], v);
    } else if (c == 65) {
        #pragma unroll
        for (int j = 0; j < 64; j++) v = fmaf(W2[k * 64 + j], a_dst2[j], v);
    }
    g_W2e[idx] = v;
}

// ---------------- adjacency build ----------------
__global__ __launch_bounds__(256) void scatter_kernel(const int* __restrict__ src,
                                                      const int* __restrict__ dst) {
    int i = blockIdx.x * 256 + threadIdx.x;
    if (i >= NEDGES) return;
    int d = dst[i];
    int pos = atomicAdd(&g_cnt[d], 1);
    if (pos < DEGCAP) g_adj[d * DEGCAP + pos] = src[i];
}

// ---------------- extended GEMM: [h | alpha_s | alpha_d] = x @ Wext ----------------
// 128 nodes x 80 cols per block, 160 threads, 8x8 register tile per thread.
template<int KDIM, bool LAYER1>
__global__ __launch_bounds__(160) void gemm_ext_kernel(const float* __restrict__ x,
                                                       const float* __restrict__ Wext,
                                                       float* __restrict__ hout,
                                                       float* __restrict__ as,
                                                       float* __restrict__ ad) {
    __shared__ float xs[128][36];   // 32-k chunk, padded (stride 36 words: 16B aligned, bank-clean)
    __shared__ float ws[32][CO];

    const int tid  = threadIdx.x;
    const int cw   = tid % 10;      // col group: cols cw*8 .. cw*8+7
    const int nw   = tid / 10;      // node group: nodes nw*8 .. nw*8+7
    const int nbase = blockIdx.x * 128;

    float acc[8][8] = {};

    for (int kc = 0; kc < KDIM / 32; kc++) {
        // load W chunk: 32 x 80 floats = 640 float4
        for (int f = tid; f < 640; f += 160) {
            int k = f / 20, q = f % 20;
            float4 v = *(const float4*)(Wext + (kc * 32 + k) * CO + q * 4);
            *(float4*)&ws[k][q * 4] = v;
        }
        // load x chunk: 128 rows x 32 cols = 1024 float4
        for (int f = tid; f < 1024; f += 160) {
            int r = f >> 3, q = f & 7;
            int row = nbase + r;
            float4 v = make_float4(0.f, 0.f, 0.f, 0.f);
            if (row < NNODES) v = *(const float4*)(x + (long long)row * KDIM + kc * 32 + q * 4);
            *(float4*)&xs[r][q * 4] = v;
        }
        __syncthreads();

        #pragma unroll
        for (int k = 0; k < 32; k++) {
            float4 w0 = *(const float4*)&ws[k][cw * 8];
            float4 w1 = *(const float4*)&ws[k][cw * 8 + 4];
            #pragma unroll
            for (int i = 0; i < 8; i++) {
                float xv = xs[nw * 8 + i][k];
                acc[i][0] = fmaf(xv, w0.x, acc[i][0]);
                acc[i][1] = fmaf(xv, w0.y, acc[i][1]);
                acc[i][2] = fmaf(xv, w0.z, acc[i][2]);
                acc[i][3] = fmaf(xv, w0.w, acc[i][3]);
                acc[i][4] = fmaf(xv, w1.x, acc[i][4]);
                acc[i][5] = fmaf(xv, w1.y, acc[i][5]);
                acc[i][6] = fmaf(xv, w1.z, acc[i][6]);
                acc[i][7] = fmaf(xv, w1.w, acc[i][7]);
            }
        }
        __syncthreads();
    }

    #pragma unroll
    for (int i = 0; i < 8; i++) {
        int n = nbase + nw * 8 + i;
        if (n >= NNODES) break;
        if (cw < 8) {
            *(float4*)(hout + (long long)n * 64 + cw * 8)     = make_float4(acc[i][0], acc[i][1], acc[i][2], acc[i][3]);
            *(float4*)(hout + (long long)n * 64 + cw * 8 + 4) = make_float4(acc[i][4], acc[i][5], acc[i][6], acc[i][7]);
        } else if (cw == 8) {
            if (LAYER1) {
                *(float4*)(as + n * 8)     = make_float4(acc[i][0], acc[i][1], acc[i][2], acc[i][3]);
                *(float4*)(as + n * 8 + 4) = make_float4(acc[i][4], acc[i][5], acc[i][6], acc[i][7]);
            } else {
                as[n] = acc[i][0];
                ad[n] = acc[i][1];
            }
        } else { // cw == 9
            if (LAYER1) {
                *(float4*)(ad + n * 8)     = make_float4(acc[i][0], acc[i][1], acc[i][2], acc[i][3]);
                *(float4*)(ad + n * 8 + 4) = make_float4(acc[i][4], acc[i][5], acc[i][6], acc[i][7]);
            }
        }
    }
}

// ---------------- layer-1 gather (warp per dst node) + fused ELU finalize ----------------
__global__ __launch_bounds__(256) void gather1_kernel(const float* __restrict__ b1) {
    const int warp = (blockIdx.x * 256 + threadIdx.x) >> 5;
    const int lane = threadIdx.x & 31;
    if (warp >= NNODES) return;
    const int d    = warp;
    const int head = lane >> 2;

    const float ad_h = g_ad1[d * H1N + head];

    int c = g_cnt[d];
    c = c > DEGCAP ? DEGCAP : c;
    const int* row = g_adj + d * DEGCAP;
    int e0 = (lane      < c) ? row[lane]      : 0;
    int e1 = (lane + 32 < c) ? row[lane + 32] : 0;

    float accx = 0.f, accy = 0.f, den = 0.f;
    {   // self-loop
        float p = pe(g_as1[d * H1N + head] + ad_h);
        float2 hv = *(const float2*)(g_h1 + (long long)d * 64 + 2 * lane);
        accx = hv.x * p; accy = hv.y * p; den = p;
    }

    #pragma unroll 4
    for (int j = 0; j < c; j++) {
        int s = __shfl_sync(0xffffffffu, (j < 32) ? e0 : e1, j & 31);
        float p = pe(g_as1[s * H1N + head] + ad_h);
        float2 hv = *(const float2*)(g_h1 + (long long)s * 64 + 2 * lane);
        accx = fmaf(hv.x, p, accx);
        accy = fmaf(hv.y, p, accy);
        den += p;
    }

    float inv = 1.f / (den + 1e-16f);
    float v0 = accx * inv + b1[2 * lane];
    float v1 = accy * inv + b1[2 * lane + 1];
    v0 = v0 > 0.f ? v0 : expm1f(v0);
    v1 = v1 > 0.f ? v1 : expm1f(v1);
    *(float2*)(g_f2 + (long long)d * 64 + 2 * lane) = make_float2(v0, v1);
}

// ---------------- layer-2 gather (warp per dst node) + fused log_softmax ----------------
__global__ __launch_bounds__(256) void gather2_kernel(const float* __restrict__ b2,
                                                      float* __restrict__ out) {
    const int warp = (blockIdx.x * 256 + threadIdx.x) >> 5;
    const int lane = threadIdx.x & 31;
    if (warp >= NNODES) return;
    const int d = warp;

    const float ad_d = g_ad2[d];

    int c = g_cnt[d];
    c = c > DEGCAP ? DEGCAP : c;
    const int* row = g_adj + d * DEGCAP;
    int e0 = (lane      < c) ? row[lane]      : 0;
    int e1 = (lane + 32 < c) ? row[lane + 32] : 0;

    float p0 = (lane      < c) ? pe(g_as2[e0] + ad_d) : 0.f;
    float p1 = (lane + 32 < c) ? pe(g_as2[e1] + ad_d) : 0.f;

    float accx, accy, den;
    {   // self-loop
        float p = pe(g_as2[d] + ad_d);
        float2 hv = *(const float2*)(g_h2 + (long long)d * 64 + 2 * lane);
        accx = hv.x * p; accy = hv.y * p; den = p;
    }

    #pragma unroll 4
    for (int j = 0; j < c; j++) {
        int   s = __shfl_sync(0xffffffffu, (j < 32) ? e0 : e1, j & 31);
        float p = __shfl_sync(0xffffffffu, (j < 32) ? p0 : p1, j & 31);
        float2 hv = *(const float2*)(g_h2 + (long long)s * 64 + 2 * lane);
        accx = fmaf(hv.x, p, accx);
        accy = fmaf(hv.y, p, accy);
        den += p;
    }

    float inv = 1.f / (den + 1e-16f);
    float v0 = accx * inv + b2[2 * lane];
    float v1 = accy * inv + b2[2 * lane + 1];

    float mx = fmaxf(v0, v1);
    #pragma unroll
    for (int o = 16; o > 0; o >>= 1) mx = fmaxf(mx, __shfl_xor_sync(0xffffffffu, mx, o));
    float se = __expf(v0 - mx) + __expf(v1 - mx);
    #pragma unroll
    for (int o = 16; o > 0; o >>= 1) se += __shfl_xor_sync(0xffffffffu, se, o);
    float ls = mx + logf(se);

    *(float2*)(out + (long long)d * 64 + 2 * lane) = make_float2(v0 - ls, v1 - ls);
}

// ---------------- launch ----------------
extern "C" void kernel_launch(void* const* d_in, const int* in_sizes, int n_in,
                              void* d_out, int out_size) {
    const float* x      = (const float*)d_in[0];
    const int*   eidx   = (const int*)  d_in[1];
    const float* W1     = (const float*)d_in[2];
    const float* a_src1 = (const float*)d_in[3];
    const float* a_dst1 = (const float*)d_in[4];
    const float* b1     = (const float*)d_in[5];
    const float* W2     = (const float*)d_in[6];
    const float* a_src2 = (const float*)d_in[7];
    const float* a_dst2 = (const float*)d_in[8];
    const float* b2     = (const float*)d_in[9];
    float* out = (float*)d_out;

    const int* src = eidx;
    const int* dst = eidx + NEDGES;

    float *p_h1, *p_as1, *p_ad1, *p_f2, *p_h2, *p_as2, *p_ad2, *p_W1e, *p_W2e;
    int* p_cnt;
    cudaGetSymbolAddress((void**)&p_h1,  g_h1);
    cudaGetSymbolAddress((void**)&p_as1, g_as1);
    cudaGetSymbolAddress((void**)&p_ad1, g_ad1);
    cudaGetSymbolAddress((void**)&p_f2,  g_f2);
    cudaGetSymbolAddress((void**)&p_h2,  g_h2);
    cudaGetSymbolAddress((void**)&p_as2, g_as2);
    cudaGetSymbolAddress((void**)&p_ad2, g_ad2);
    cudaGetSymbolAddress((void**)&p_W1e, g_W1e);
    cudaGetSymbolAddress((void**)&p_W2e, g_W2e);
    cudaGetSymbolAddress((void**)&p_cnt, g_cnt);

    const int TB = 256;
    // prep + adjacency
    prep1_kernel<<<(FIN * CO + TB - 1) / TB, TB>>>(W1, a_src1, a_dst1);
    prep2_kernel<<<(F1 * CO + TB - 1) / TB, TB>>>(W2, a_src2, a_dst2);
    cudaMemsetAsync(p_cnt, 0, NNODES * sizeof(int));
    scatter_kernel<<<(NEDGES + TB - 1) / TB, TB>>>(src, dst);
    // layer 1
    gemm_ext_kernel<FIN, true><<<(NNODES + 127) / 128, 160>>>(x, p_W1e, p_h1, p_as1, p_ad1);
    gather1_kernel<<<(NNODES * 32 + TB - 1) / TB, TB>>>(b1);
    // layer 2
    gemm_ext_kernel<F1, false><<<(NNODES + 127) / 128, 160>>>(p_f2, p_W2e, p_h2, p_as2, p_ad2);
    gather2_kernel<<<(NNODES * 32 + TB - 1) / TB, TB>>>(b2, out);
}